// round 1
// baseline (speedup 1.0000x reference)
#include <cuda_runtime.h>
#include <math.h>

// Problem constants (from reference: x [L=4096, B=4, D=1024] fp32)
#define L  4096
#define B  4
#define D  1024
#define BD (B * D)          // 4096 channels
#define C  32               // time chunks
#define LC (L / C)          // 128 steps per chunk

// Scratch (static __device__ arrays — no allocation allowed)
__device__ float2 g_c[D];            // per-channel multiplier c
__device__ float2 g_cLc[D];          // c^LC
__device__ float2 g_end[C * BD];     // local chunk end-states (zero-init scans)
__device__ float2 g_Sprev[C * BD];   // true state entering each chunk

// ---------------------------------------------------------------------------
// K0: per-channel coefficients in double precision.
//   c = exp(-exp(lmlg)) * (cos(theta) + i sin(theta));  also c^LC by squaring.
// ---------------------------------------------------------------------------
__global__ void k0_coeffs(const float* __restrict__ lmlg,
                          const float* __restrict__ theta) {
    int d = blockIdx.x * blockDim.x + threadIdx.x;
    if (d >= D) return;
    double g  = exp(-exp((double)lmlg[d]));
    double th = (double)theta[d];
    double cr = g * cos(th);
    double ci = g * sin(th);
    g_c[d] = make_float2((float)cr, (float)ci);
    // c^128 = ((c^2)^2 ...)^2, 7 squarings, in double
    double ar = cr, ai = ci;
#pragma unroll
    for (int i = 0; i < 7; i++) {
        double nr = ar * ar - ai * ai;
        double ni = 2.0 * ar * ai;
        ar = nr; ai = ni;
    }
    g_cLc[d] = make_float2((float)ar, (float)ai);
}

// ---------------------------------------------------------------------------
// K1: local scan per (chunk, channel) with zero initial state; store end state.
// tid = chunk*BD + b*D + d  -> lanes within a warp have adjacent d => coalesced.
// ---------------------------------------------------------------------------
__global__ void k1_local_end(const float* __restrict__ x) {
    int tid = blockIdx.x * blockDim.x + threadIdx.x;
    if (tid >= C * BD) return;
    int chunk = tid / BD;
    int bd    = tid - chunk * BD;
    int d     = bd & (D - 1);
    float2 c = g_c[d];
    float sr = 0.f, si = 0.f;
    const float* xp = x + (size_t)chunk * LC * BD + bd;
#pragma unroll 8
    for (int n = 0; n < LC; n++) {
        float xv = xp[(size_t)n * BD];
        float nr = fmaf(c.x, sr, fmaf(-c.y, si, xv));
        float ni = fmaf(c.y, sr, c.x * si);
        sr = nr; si = ni;
    }
    g_end[tid] = make_float2(sr, si);
}

// ---------------------------------------------------------------------------
// K2: scan over chunk boundaries. S[-1] = last_conv_init (real).
//     S entering chunk j stored in g_Sprev[j*BD + bd].
// ---------------------------------------------------------------------------
__global__ void k2_chunk_scan(const float* __restrict__ last_conv_init) {
    int bd = blockIdx.x * blockDim.x + threadIdx.x;
    if (bd >= BD) return;
    int d = bd & (D - 1);
    float2 A = g_cLc[d];
    float sr = last_conv_init[d], si = 0.f;
    g_Sprev[bd] = make_float2(sr, si);
#pragma unroll
    for (int j = 0; j < C - 1; j++) {
        float2 e = g_end[j * BD + bd];
        float nr = A.x * sr - A.y * si + e.x;
        float ni = A.x * si + A.y * sr + e.y;
        sr = nr; si = ni;
        g_Sprev[(j + 1) * BD + bd] = make_float2(sr, si);
    }
}

// ---------------------------------------------------------------------------
// K3: final pass — rerun local scan seeded with true prefix, write Re(s)*x.
// ---------------------------------------------------------------------------
__global__ void k3_finalize(const float* __restrict__ x,
                            float* __restrict__ out) {
    int tid = blockIdx.x * blockDim.x + threadIdx.x;
    if (tid >= C * BD) return;
    int chunk = tid / BD;
    int bd    = tid - chunk * BD;
    int d     = bd & (D - 1);
    float2 c = g_c[d];
    float2 S = g_Sprev[tid];
    float sr = S.x, si = S.y;
    size_t base = (size_t)chunk * LC * BD + bd;
    const float* xp = x + base;
    float*       op = out + base;
#pragma unroll 8
    for (int n = 0; n < LC; n++) {
        float xv = xp[(size_t)n * BD];
        float nr = fmaf(c.x, sr, fmaf(-c.y, si, xv));
        float ni = fmaf(c.y, sr, c.x * si);
        sr = nr; si = ni;
        op[(size_t)n * BD] = sr * xv;
    }
}

// ---------------------------------------------------------------------------
extern "C" void kernel_launch(void* const* d_in, const int* in_sizes, int n_in,
                              void* d_out, int out_size) {
    const float* x    = (const float*)d_in[0];  // [L,B,D]
    const float* lmlg = (const float*)d_in[1];  // [D]
    const float* th   = (const float*)d_in[2];  // [D]
    const float* lci  = (const float*)d_in[3];  // [D]
    float* out = (float*)d_out;

    k0_coeffs<<<(D + 255) / 256, 256>>>(lmlg, th);
    k1_local_end<<<(C * BD + 255) / 256, 256>>>(x);
    k2_chunk_scan<<<(BD + 255) / 256, 256>>>(lci);
    k3_finalize<<<(C * BD + 255) / 256, 256>>>(x, out);
}